// round 15
// baseline (speedup 1.0000x reference)
#include <cuda_runtime.h>
#include <cstdint>

// HardLinearAttention — algebraic collapse of P@Z@M@Z^T@Q@Z.
// d=1024, n=8192, Z is (2d+1, n+1) = (2049, 8193) float32.
//
//   v[j]  = sum_{k<8192} Z[j,k] * Z[2048,k]          (j < 1024)
//   r[k]  = sum_{j<1024} v[j] * (Z[1024+j,k] - Z[j,k])
//   out   = Z;  out[2048,k] += (alpha/8192) * r[k]
//
// Direction-balanced plan (HW sustains ~3.4 TB/s per direction, overlapped):
//   k1: TMA-load rows 0..1023 + u  -> v partials AND copy rows 0..1023 to out
//       (32 MB read + 32 MB write, balanced)
//   k2: rows 1024..2047: copy + acc; a-rows re-read from L2
//       (34 MB DRAM read + 34 MB write, a-rows L2-hit)
//   k3: reduce partials into row 2048

#define D       1024
#define NCOLS   8192
#define S       8193          // n+1 (row stride)
#define JCHUNKS 16
#define JPER    (D / JCHUNKS) // 64
#define CHUNK   2048          // k1 chunk, floats
#define NCHUNK  (NCOLS / CHUNK)
#define PADF    4
#define ROWB    (CHUNK + PADF)
#define CHUNK_BYTES   ((ROWB) * 4)          // 8208, mult of 16
#define U_BYTES       (CHUNK * 4)           // 8192
#define TX_BYTES      (2 * CHUNK_BYTES + U_BYTES)

__device__ float g_v[D];
__device__ float g_part[JCHUNKS * S];

__device__ __forceinline__ unsigned smem_u32(const void* p) {
    return (unsigned)__cvta_generic_to_shared(p);
}
__device__ __forceinline__ void mbar_init(unsigned mbar, unsigned cnt) {
    asm volatile("mbarrier.init.shared.b64 [%0], %1;" :: "r"(mbar), "r"(cnt) : "memory");
}
__device__ __forceinline__ void mbar_expect_tx(unsigned mbar, unsigned bytes) {
    asm volatile("mbarrier.arrive.expect_tx.shared.b64 _, [%0], %1;"
                 :: "r"(mbar), "r"(bytes) : "memory");
}
__device__ __forceinline__ void mbar_wait(unsigned mbar, unsigned phase) {
    asm volatile(
        "{\n\t"
        ".reg .pred P;\n\t"
        "WAIT_%=:\n\t"
        "mbarrier.try_wait.parity.shared.b64 P, [%0], %1;\n\t"
        "@P bra DONE_%=;\n\t"
        "bra WAIT_%=;\n\t"
        "DONE_%=:\n\t"
        "}"
        :: "r"(mbar), "r"(phase) : "memory");
}
__device__ __forceinline__ void bulk_ld(unsigned dst, const void* src,
                                        unsigned bytes, unsigned mbar) {
    asm volatile(
        "cp.async.bulk.shared::cta.global.mbarrier::complete_tx::bytes [%0], [%1], %2, [%3];"
        :: "r"(dst), "l"(src), "r"(bytes), "r"(mbar) : "memory");
}

// ---------------- kernel 1: v + copy of rows 0..1023 via bulk-TMA --------
// Block b handles rows {b, b+512}. TMA loads (read direction, proven
// 3.36 TB/s) + plain STG copies (write direction, otherwise idle).
__global__ void __launch_bounds__(256) k_compute_v(const float* __restrict__ Z,
                                                   float* __restrict__ out) {
    __shared__ __align__(16) float sa[2][ROWB];
    __shared__ __align__(16) float sb[2][ROWB];
    __shared__ __align__(16) float su[2][CHUNK];
    __shared__ __align__(8)  unsigned long long mbar[2];

    const int b   = blockIdx.x;                 // 0..511
    const int tid = threadIdx.x;
    const int h   = b & 3;                      // smem read shift

    const float* __restrict__ ra = Z + (size_t)b * S - h;          // 16B aligned
    const float* __restrict__ rb = Z + (size_t)(b + 512) * S - h;  // 16B aligned
    const float* __restrict__ u  = Z + (size_t)2048 * S;           // 16B aligned

    float* __restrict__ oa = out + (size_t)b * S;
    float* __restrict__ ob = out + (size_t)(b + 512) * S;

    const unsigned mb0 = smem_u32(&mbar[0]);
    if (tid == 0) { mbar_init(mb0, 1); mbar_init(mb0 + 8, 1); }
    __syncthreads();

    auto issue = [&](int c) {
        const int st = c & 1;
        const unsigned mb = mb0 + 8u * st;
        mbar_expect_tx(mb, TX_BYTES);
        const int k0 = c * CHUNK;
        bulk_ld(smem_u32(&sa[st][0]), ra + k0, CHUNK_BYTES, mb);
        bulk_ld(smem_u32(&sb[st][0]), rb + k0, CHUNK_BYTES, mb);
        bulk_ld(smem_u32(&su[st][0]), u  + k0, U_BYTES,     mb);
    };

    if (tid == 0) { issue(0); issue(1); }

    float acc0 = 0.f, acc1 = 0.f;

    for (int c = 0; c < NCHUNK; c++) {
        const int st = c & 1;
        const int k0 = c * CHUNK;
        mbar_wait(mb0 + 8u * st, (c >> 1) & 1);

        #pragma unroll
        for (int s = 0; s < CHUNK / 256; s++) {     // 8 iters
            const int i = tid + 256 * s;
            const float uk = su[st][i];
            const float va = sa[st][i + h];
            const float vb = sb[st][i + h];
            oa[k0 + i] = va;                        // copy (write direction)
            ob[k0 + i] = vb;
            acc0 += va * uk;
            acc1 += vb * uk;
        }

        if (c + 2 < NCHUNK) {
            __syncthreads();                        // all done reading buffer st
            if (tid == 0) issue(c + 2);
        }
    }

    // tail column 8192 (outside the 4 chunks)
    if (tid == 0) {
        oa[NCOLS] = Z[(size_t)b * S + NCOLS];
        ob[NCOLS] = Z[(size_t)(b + 512) * S + NCOLS];
    }

    // block reduce (two values)
    #pragma unroll
    for (int o = 16; o > 0; o >>= 1) {
        acc0 += __shfl_down_sync(0xffffffffu, acc0, o);
        acc1 += __shfl_down_sync(0xffffffffu, acc1, o);
    }
    __shared__ float s0[8], s1[8];
    const int lane = tid & 31;
    const int w    = tid >> 5;
    if (lane == 0) { s0[w] = acc0; s1[w] = acc1; }
    __syncthreads();
    if (w == 0) {
        acc0 = (lane < 8) ? s0[lane] : 0.f;
        acc1 = (lane < 8) ? s1[lane] : 0.f;
        #pragma unroll
        for (int o = 4; o > 0; o >>= 1) {
            acc0 += __shfl_down_sync(0xffffffffu, acc0, o);
            acc1 += __shfl_down_sync(0xffffffffu, acc1, o);
        }
        if (lane == 0) { g_v[b] = acc0; g_v[b + 512] = acc1; }
    }
}

// ---------------- kernel 2: copy rows 1024..2047 + acc -------------------
// a-rows (0..1023) are read for the (b-a) term but NOT copied (k1 did that);
// they should be L2-resident from k1's stream.
__global__ void __launch_bounds__(256) k_copy_acc(const float* __restrict__ Z,
                                                  float* __restrict__ out) {
    const int jc = blockIdx.y;
    const int k  = blockIdx.x * 256 + threadIdx.x;

    __shared__ float vs[JPER];
    if (threadIdx.x < JPER) vs[threadIdx.x] = g_v[jc * JPER + threadIdx.x];
    __syncthreads();

    if (k >= S) return;

    const int j0 = jc * JPER;
    float acc = 0.f;
    #pragma unroll 8
    for (int jj = 0; jj < JPER; jj++) {
        const size_t ia = (size_t)(j0 + jj) * S + k;
        const size_t ib = (size_t)(j0 + jj + D) * S + k;
        const float a = Z[ia];          // L2-resident (k1 streamed it)
        const float b = Z[ib];          // DRAM
        out[ib] = b;                    // copy b-row only
        acc += vs[jj] * (b - a);
    }
    g_part[(size_t)jc * S + k] = acc;
}

// ---------------- kernel 3: reduce partials, write final row 2048 --------
__global__ void __launch_bounds__(256) k_final(const float* __restrict__ Z,
                                               const float* __restrict__ alpha,
                                               float* __restrict__ out) {
    __shared__ float sp[4][64];
    const int g = threadIdx.x >> 6;             // chunk group 0..3
    const int c = threadIdx.x & 63;
    const int k = blockIdx.x * 64 + c;

    float sum = 0.f;
    if (k <= NCOLS) {
        #pragma unroll
        for (int q = 0; q < 4; q++)
            sum += g_part[(size_t)(4 * g + q) * S + k];
    }
    sp[g][c] = sum;
    __syncthreads();

    if (threadIdx.x < 64) {
        const int kk = blockIdx.x * 64 + threadIdx.x;
        if (kk <= NCOLS) {
            const float tot = sp[0][threadIdx.x] + sp[1][threadIdx.x]
                            + sp[2][threadIdx.x] + sp[3][threadIdx.x];
            const float scale = alpha[0] / (float)NCOLS;
            out[(size_t)2048 * S + kk] = Z[(size_t)2048 * S + kk] + scale * tot;
        }
    }
}

extern "C" void kernel_launch(void* const* d_in, const int* in_sizes, int n_in,
                              void* d_out, int out_size) {
    const float* Z     = (const float*)d_in[0];
    const float* alpha = (const float*)d_in[1];
    float* out         = (float*)d_out;

    k_compute_v<<<512, 256>>>(Z, out);

    dim3 g2((S + 255) / 256, JCHUNKS);
    k_copy_acc<<<g2, 256>>>(Z, out);

    k_final<<<(NCOLS + 64) / 64, 256>>>(Z, alpha, out);   // 129 blocks
}

// round 16
// speedup vs baseline: 1.0664x; 1.0664x over previous
#include <cuda_runtime.h>
#include <cstdint>

// HardLinearAttention — algebraic collapse of P@Z@M@Z^T@Q@Z.
// d=1024, n=8192, Z is (2d+1, n+1) = (2049, 8193) float32.
//
//   v[j]  = sum_{k<8192} Z[j,k] * Z[2048,k]          (j < 1024)
//   r[k]  = sum_{j<1024} v[j] * (Z[1024+j,k] - Z[j,k])
//   out   = Z;  out[2048,k] += (alpha/8192) * r[k]
//
// Direction-balanced, DMA-both-ways plan:
//   k1: bulk-TMA loads rows 0..1023 + u -> v partials; copies those rows to
//       out via bulk-TMA STORES (write direction on the async proxy, zero
//       warp-path cost). Padded-buffer stores overspill into neighbor rows
//       with identical values (out[x]=Z[x]) — benign, and cover col 8192.
//   k2: rows 1024..2047: copy + acc (a-rows re-read, partially L2-hot)
//   k3: reduce partials into row 2048

#define D       1024
#define NCOLS   8192
#define S       8193          // n+1 (row stride)
#define JCHUNKS 16
#define JPER    (D / JCHUNKS) // 64
#define CHUNK   1024          // k1 chunk, floats
#define NCHUNK  (NCOLS / CHUNK)   // 8
#define NBUF    3
#define PADF    4
#define ROWB    (CHUNK + PADF)
#define CHUNK_BYTES   ((ROWB) * 4)          // 4112, mult of 16
#define U_BYTES       (CHUNK * 4)           // 4096
#define TX_BYTES      (2 * CHUNK_BYTES + U_BYTES)

__device__ float g_v[D];
__device__ float g_part[JCHUNKS * S];

__device__ __forceinline__ unsigned smem_u32(const void* p) {
    return (unsigned)__cvta_generic_to_shared(p);
}
__device__ __forceinline__ void mbar_init(unsigned mbar, unsigned cnt) {
    asm volatile("mbarrier.init.shared.b64 [%0], %1;" :: "r"(mbar), "r"(cnt) : "memory");
}
__device__ __forceinline__ void mbar_expect_tx(unsigned mbar, unsigned bytes) {
    asm volatile("mbarrier.arrive.expect_tx.shared.b64 _, [%0], %1;"
                 :: "r"(mbar), "r"(bytes) : "memory");
}
__device__ __forceinline__ void mbar_wait(unsigned mbar, unsigned phase) {
    asm volatile(
        "{\n\t"
        ".reg .pred P;\n\t"
        "WAIT_%=:\n\t"
        "mbarrier.try_wait.parity.shared.b64 P, [%0], %1;\n\t"
        "@P bra DONE_%=;\n\t"
        "bra WAIT_%=;\n\t"
        "DONE_%=:\n\t"
        "}"
        :: "r"(mbar), "r"(phase) : "memory");
}
__device__ __forceinline__ void bulk_ld(unsigned dst, const void* src,
                                        unsigned bytes, unsigned mbar) {
    asm volatile(
        "cp.async.bulk.shared::cta.global.mbarrier::complete_tx::bytes [%0], [%1], %2, [%3];"
        :: "r"(dst), "l"(src), "r"(bytes), "r"(mbar) : "memory");
}
__device__ __forceinline__ void bulk_st(void* dst, unsigned src, unsigned bytes) {
    asm volatile(
        "cp.async.bulk.global.shared::cta.bulk_group [%0], [%1], %2;"
        :: "l"(dst), "r"(src), "r"(bytes) : "memory");
}
__device__ __forceinline__ void bulk_st_commit() {
    asm volatile("cp.async.bulk.commit_group;" ::: "memory");
}
template <int N>
__device__ __forceinline__ void bulk_st_wait() {
    asm volatile("cp.async.bulk.wait_group %0;" :: "n"(N) : "memory");
}

// ---------------- kernel 1: v + copy of rows 0..1023, DMA both ways ------
// Block b handles rows {b, b+512} (same phase h = b&3). Loads from the
// 16B-aligned floor (Z + b*S - h); stores the whole padded buffer back to
// out + b*S - h + k0 (16B-aligned dst/src/size). Overspill is benign.
__global__ void __launch_bounds__(256) k_compute_v(const float* __restrict__ Z,
                                                   float* __restrict__ out) {
    __shared__ __align__(16) float sa[NBUF][ROWB];
    __shared__ __align__(16) float sb[NBUF][ROWB];
    __shared__ __align__(16) float su[NBUF][CHUNK];
    __shared__ __align__(8)  unsigned long long mbar[NBUF];

    const int b   = blockIdx.x;                 // 0..511
    const int tid = threadIdx.x;
    const int h   = b & 3;                      // smem read shift

    const float* __restrict__ ra = Z + (size_t)b * S - h;          // 16B aligned
    const float* __restrict__ rb = Z + (size_t)(b + 512) * S - h;  // 16B aligned
    const float* __restrict__ u  = Z + (size_t)2048 * S;           // 16B aligned

    float* __restrict__ oa = out + (size_t)b * S - h;              // 16B aligned
    float* __restrict__ ob = out + (size_t)(b + 512) * S - h;      // 16B aligned

    const unsigned mb0 = smem_u32(&mbar[0]);
    if (tid == 0) {
        #pragma unroll
        for (int q = 0; q < NBUF; q++) mbar_init(mb0 + 8u * q, 1);
    }
    __syncthreads();

    auto issue_load = [&](int c) {
        const int st = c % NBUF;
        const unsigned mb = mb0 + 8u * st;
        mbar_expect_tx(mb, TX_BYTES);
        const int k0 = c * CHUNK;
        bulk_ld(smem_u32(&sa[st][0]), ra + k0, CHUNK_BYTES, mb);
        bulk_ld(smem_u32(&sb[st][0]), rb + k0, CHUNK_BYTES, mb);
        bulk_ld(smem_u32(&su[st][0]), u  + k0, U_BYTES,     mb);
    };

    if (tid == 0) { issue_load(0); issue_load(1); }

    float acc0 = 0.f, acc1 = 0.f;

    for (int c = 0; c < NCHUNK; c++) {
        const int st = c % NBUF;
        const int k0 = c * CHUNK;
        mbar_wait(mb0 + 8u * st, (c / NBUF) & 1);

        // copy via TMA store: full padded buffer, aligned; spill writes
        // identical values into neighbor rows' copy regions.
        if (tid == 0) {
            bulk_st(oa + k0, smem_u32(&sa[st][0]), CHUNK_BYTES);
            bulk_st(ob + k0, smem_u32(&sb[st][0]), CHUNK_BYTES);
            bulk_st_commit();
        }

        #pragma unroll
        for (int s = 0; s < CHUNK / 256; s++) {     // 4 iters
            const int i = tid + 256 * s;
            const float uk = su[st][i];
            acc0 += sa[st][i + h] * uk;
            acc1 += sb[st][i + h] * uk;
        }

        if (c + 2 < NCHUNK) {
            __syncthreads();                        // all threads done with buf (c-1)%NBUF
            if (tid == 0) {
                bulk_st_wait<1>();                  // store of chunk c-1 (same buf) done
                issue_load(c + 2);
            }
        }
    }
    if (tid == 0) bulk_st_wait<0>();                // drain stores before exit

    // block reduce (two values)
    #pragma unroll
    for (int o = 16; o > 0; o >>= 1) {
        acc0 += __shfl_down_sync(0xffffffffu, acc0, o);
        acc1 += __shfl_down_sync(0xffffffffu, acc1, o);
    }
    __shared__ float s0[8], s1[8];
    const int lane = tid & 31;
    const int w    = tid >> 5;
    if (lane == 0) { s0[w] = acc0; s1[w] = acc1; }
    __syncthreads();
    if (w == 0) {
        acc0 = (lane < 8) ? s0[lane] : 0.f;
        acc1 = (lane < 8) ? s1[lane] : 0.f;
        #pragma unroll
        for (int o = 4; o > 0; o >>= 1) {
            acc0 += __shfl_down_sync(0xffffffffu, acc0, o);
            acc1 += __shfl_down_sync(0xffffffffu, acc1, o);
        }
        if (lane == 0) { g_v[b] = acc0; g_v[b + 512] = acc1; }
    }
}

// ---------------- kernel 2: copy rows 1024..2047 + acc -------------------
// a-rows (0..1023) re-read for the (b-a) term (not copied — k1 did that).
__global__ void __launch_bounds__(256) k_copy_acc(const float* __restrict__ Z,
                                                  float* __restrict__ out) {
    const int jc = blockIdx.y;
    const int k  = blockIdx.x * 256 + threadIdx.x;

    __shared__ float vs[JPER];
    if (threadIdx.x < JPER) vs[threadIdx.x] = g_v[jc * JPER + threadIdx.x];
    __syncthreads();

    if (k >= S) return;

    const int j0 = jc * JPER;
    float acc = 0.f;
    #pragma unroll 8
    for (int jj = 0; jj < JPER; jj++) {
        const size_t ia = (size_t)(j0 + jj) * S + k;
        const size_t ib = (size_t)(j0 + jj + D) * S + k;
        const float a = Z[ia];
        const float b = Z[ib];
        out[ib] = b;                    // copy b-row only
        acc += vs[jj] * (b - a);
    }
    g_part[(size_t)jc * S + k] = acc;
}

// ---------------- kernel 3: reduce partials, write final row 2048 --------
__global__ void __launch_bounds__(256) k_final(const float* __restrict__ Z,
                                               const float* __restrict__ alpha,
                                               float* __restrict__ out) {
    __shared__ float sp[4][64];
    const int g = threadIdx.x >> 6;             // chunk group 0..3
    const int c = threadIdx.x & 63;
    const int k = blockIdx.x * 64 + c;

    float sum = 0.f;
    if (k <= NCOLS) {
        #pragma unroll
        for (int q = 0; q < 4; q++)
            sum += g_part[(size_t)(4 * g + q) * S + k];
    }
    sp[g][c] = sum;
    __syncthreads();

    if (threadIdx.x < 64) {
        const int kk = blockIdx.x * 64 + threadIdx.x;
        if (kk <= NCOLS) {
            const float tot = sp[0][threadIdx.x] + sp[1][threadIdx.x]
                            + sp[2][threadIdx.x] + sp[3][threadIdx.x];
            const float scale = alpha[0] / (float)NCOLS;
            out[(size_t)2048 * S + kk] = Z[(size_t)2048 * S + kk] + scale * tot;
        }
    }
}

extern "C" void kernel_launch(void* const* d_in, const int* in_sizes, int n_in,
                              void* d_out, int out_size) {
    const float* Z     = (const float*)d_in[0];
    const float* alpha = (const float*)d_in[1];
    float* out         = (float*)d_out;

    k_compute_v<<<512, 256>>>(Z, out);

    dim3 g2((S + 255) / 256, JCHUNKS);
    k_copy_acc<<<g2, 256>>>(Z, out);

    k_final<<<(NCOLS + 64) / 64, 256>>>(Z, alpha, out);   // 129 blocks
}